// round 2
// baseline (speedup 1.0000x reference)
#include <cuda_runtime.h>
#include <math.h>

#define N_NODES 100000
#define N_EDGES 1600000
#define IN_DIM 128
#define HID 64
#define NCLS 40

// Scratch (static device arrays: allowed; no runtime allocation)
__device__ float g_bufA[(size_t)N_NODES * HID];
__device__ float g_bufB[(size_t)N_NODES * HID];

// ---------------------------------------------------------------------------
// Y[M x 64] = act(X[M x K]) @ W[K x 64] + b      (act = relu on input if RELU_IN)
// block = 256 threads, 64 nodes per block, 4 nodes x 4 cols per thread.
// ---------------------------------------------------------------------------
template <int K, bool RELU_IN>
__global__ void gemm64(const float* __restrict__ X, const float* __restrict__ W,
                       const float* __restrict__ b, float* __restrict__ Y, int M) {
    __shared__ float xs[64][65];   // padded against bank conflicts
    __shared__ float ws[64][64];

    const int tid = threadIdx.x;
    const int m0  = blockIdx.x * 64;
    const int cg  = tid & 15;   // col group  -> cols 4*cg .. 4*cg+3
    const int ng  = tid >> 4;   // node group -> nodes 4*ng .. 4*ng+3

    float acc[4][4];
#pragma unroll
    for (int i = 0; i < 4; i++)
#pragma unroll
        for (int j = 0; j < 4; j++) acc[i][j] = 0.f;

    for (int kc = 0; kc < K; kc += 64) {
        // stage X tile [64 nodes x 64 k]
#pragma unroll
        for (int t = tid; t < 64 * 64; t += 256) {
            int n = t >> 6, k = t & 63;
            float v = 0.f;
            if (m0 + n < M) v = X[(size_t)(m0 + n) * K + kc + k];
            if (RELU_IN) v = fmaxf(v, 0.f);
            xs[n][k] = v;
        }
        // stage W tile [64 k x 64 cols]
#pragma unroll
        for (int t = tid; t < 64 * 64; t += 256) {
            int k = t >> 6, c = t & 63;
            ws[k][c] = W[(size_t)(kc + k) * 64 + c];
        }
        __syncthreads();

#pragma unroll 8
        for (int k = 0; k < 64; k++) {
            float4 w = *(const float4*)&ws[k][cg * 4];
#pragma unroll
            for (int i = 0; i < 4; i++) {
                float xv = xs[ng * 4 + i][k];
                acc[i][0] = fmaf(xv, w.x, acc[i][0]);
                acc[i][1] = fmaf(xv, w.y, acc[i][1]);
                acc[i][2] = fmaf(xv, w.z, acc[i][2]);
                acc[i][3] = fmaf(xv, w.w, acc[i][3]);
            }
        }
        __syncthreads();
    }

    float4 bias = *(const float4*)&b[cg * 4];
#pragma unroll
    for (int i = 0; i < 4; i++) {
        int n = m0 + ng * 4 + i;
        if (n < M) {
            float4 o;
            o.x = acc[i][0] + bias.x;
            o.y = acc[i][1] + bias.y;
            o.z = acc[i][2] + bias.z;
            o.w = acc[i][3] + bias.w;
            *(float4*)&Y[(size_t)n * 64 + cg * 4] = o;
        }
    }
}

// ---------------------------------------------------------------------------
// SpMM scatter: dst[row[e]] += val[e] * src[col[e]]   (64-float rows)
// half-warp (16 lanes) per edge; one float4 gather + one red.global.add.v4.f32
// per lane. Both src and dst tiles are L2-resident (25.6 MB each).
// ---------------------------------------------------------------------------
__global__ void spmm_scatter(const int* __restrict__ rows, const int* __restrict__ cols,
                             const float* __restrict__ vals, const float* __restrict__ src,
                             float* __restrict__ dst) {
    int t = blockIdx.x * blockDim.x + threadIdx.x;
    int e = t >> 4;
    if (e >= N_EDGES) return;
    int lane = t & 15;

    int   r = __ldg(&rows[e]);
    int   c = __ldg(&cols[e]);
    float v = __ldg(&vals[e]);

    float4 m = ((const float4*)(src + (size_t)c * 64))[lane];
    m.x *= v; m.y *= v; m.z *= v; m.w *= v;

    float* d = dst + (size_t)r * 64 + lane * 4;
    asm volatile("red.global.add.v4.f32 [%0], {%1, %2, %3, %4};"
                 :: "l"(d), "f"(m.x), "f"(m.y), "f"(m.z), "f"(m.w)
                 : "memory");
}

// ---------------------------------------------------------------------------
// Classifier: logits = H[100k x 64] @ Wc[64 x 40] + bc, then log_softmax.
// Warp per node. Wc staged in smem. Lane l owns col l; lanes 0..7 also own 32+l.
// ---------------------------------------------------------------------------
__global__ void classify(const float* __restrict__ H, const float* __restrict__ Wc,
                         const float* __restrict__ bc, float* __restrict__ out) {
    __shared__ float wc[64 * NCLS];
    __shared__ float rowbuf[8][64];

    const int tid = threadIdx.x;
    for (int t = tid; t < 64 * NCLS; t += 256) wc[t] = Wc[t];
    __syncthreads();

    const int w    = tid >> 5;
    const int lane = tid & 31;
    const int node = blockIdx.x * 8 + w;
    if (node >= N_NODES) return;

    if (lane < 16) {
        float4 rv = ((const float4*)(H + (size_t)node * 64))[lane];
        *(float4*)&rowbuf[w][lane * 4] = rv;
    }
    __syncwarp();

    float a0 = bc[lane];                              // cols 0..31
    float a1 = (lane < 8) ? bc[32 + lane] : 0.f;      // cols 32..39
#pragma unroll
    for (int k = 0; k < 64; k++) {
        float r = rowbuf[w][k];
        a0 = fmaf(r, wc[k * NCLS + lane], a0);
        if (lane < 8) a1 = fmaf(r, wc[k * NCLS + 32 + lane], a1);
    }

    // warp-wide log-softmax over the 40 logits
    float mx = (lane < 8) ? fmaxf(a0, a1) : a0;
#pragma unroll
    for (int o = 16; o > 0; o >>= 1) mx = fmaxf(mx, __shfl_xor_sync(0xffffffffu, mx, o));
    float s = expf(a0 - mx) + ((lane < 8) ? expf(a1 - mx) : 0.f);
#pragma unroll
    for (int o = 16; o > 0; o >>= 1) s += __shfl_xor_sync(0xffffffffu, s, o);
    float lse = mx + logf(s);

    out[(size_t)node * NCLS + lane] = a0 - lse;
    if (lane < 8) out[(size_t)node * NCLS + 32 + lane] = a1 - lse;
}

// ---------------------------------------------------------------------------
extern "C" void kernel_launch(void* const* d_in, const int* in_sizes, int n_in,
                              void* d_out, int out_size) {
    const float* x  = (const float*)d_in[0];
    const int*   er = (const int*)  d_in[1];
    const int*   ec = (const int*)  d_in[2];
    const float* ev = (const float*)d_in[3];
    const float* W1 = (const float*)d_in[4];
    const float* b1 = (const float*)d_in[5];
    const float* W2 = (const float*)d_in[6];
    const float* b2 = (const float*)d_in[7];
    const float* Wc = (const float*)d_in[8];
    const float* bc = (const float*)d_in[9];
    float* out = (float*)d_out;

    float *bufA = nullptr, *bufB = nullptr;
    cudaGetSymbolAddress((void**)&bufA, g_bufA);
    cudaGetSymbolAddress((void**)&bufB, g_bufB);

    const int gemmGrid  = (N_NODES + 63) / 64;
    const int spmmGrid  = (int)(((size_t)N_EDGES * 16 + 255) / 256);
    const size_t bufBytes = sizeof(float) * (size_t)N_NODES * HID;

    // layer 1: support = x @ W1 + b1
    gemm64<IN_DIM, false><<<gemmGrid, 256>>>(x, W1, b1, bufA, N_NODES);
    // agg1 = A_sp @ support
    cudaMemsetAsync(bufB, 0, bufBytes, 0);
    spmm_scatter<<<spmmGrid, 256>>>(er, ec, ev, bufA, bufB);
    // layer 2: support = relu(agg1) @ W2 + b2
    gemm64<HID, true><<<gemmGrid, 256>>>(bufB, W2, b2, bufA, N_NODES);
    // agg2 = A_sp @ support
    cudaMemsetAsync(bufB, 0, bufBytes, 0);
    spmm_scatter<<<spmmGrid, 256>>>(er, ec, ev, bufA, bufB);
    // classifier + log-softmax
    classify<<<(N_NODES + 7) / 8, 256>>>(bufB, Wc, bc, out);
}

// round 3
// speedup vs baseline: 1.1763x; 1.1763x over previous
#include <cuda_runtime.h>
#include <math.h>

#define N_NODES 100000
#define N_EDGES 1600000
#define IN_DIM 128
#define HID 64
#define NCLS 40
#define NBLK ((N_NODES + 1023) / 1024)   // 98 scan blocks

typedef unsigned long long ull;

// Scratch (static device arrays: allowed; no runtime allocation)
__device__ float g_bufA[(size_t)N_NODES * HID];
__device__ float g_bufB[(size_t)N_NODES * HID];
__device__ int   g_cnt[N_NODES];          // histogram, then cursors
__device__ int   g_rowptr[N_NODES + 1];
__device__ int   g_bsum[NBLK];
__device__ int   g_ecol[N_EDGES];         // CSR-permuted cols
__device__ float g_eval[N_EDGES];         // CSR-permuted vals

// ---------------------------------------------------------------------------
// f32x2 packed helpers (Blackwell FFMA2 — only reachable via PTX)
// ---------------------------------------------------------------------------
__device__ __forceinline__ ull pack2(float x, float y) {
    ull r; asm("mov.b64 %0, {%1, %2};" : "=l"(r) : "f"(x), "f"(y)); return r;
}
__device__ __forceinline__ void ffma2(ull& d, ull a, ull b) {
    asm("fma.rn.f32x2 %0, %1, %2, %0;" : "+l"(d) : "l"(a), "l"(b));
}
__device__ __forceinline__ float2 unpack2(ull a) {
    float2 f; asm("mov.b64 {%0, %1}, %2;" : "=f"(f.x), "=f"(f.y) : "l"(a)); return f;
}

// ---------------------------------------------------------------------------
// CSR build: histogram -> 3-pass exclusive scan -> permute
// ---------------------------------------------------------------------------
__global__ void hist_kernel(const int* __restrict__ rows) {
    int e = blockIdx.x * blockDim.x + threadIdx.x;
    if (e < N_EDGES) atomicAdd(&g_cnt[rows[e]], 1);
}

__global__ void scan1_kernel() {   // per-1024-block exclusive scan + block totals
    __shared__ int sh[1024];
    int i = blockIdx.x * 1024 + threadIdx.x;
    int v = (i < N_NODES) ? g_cnt[i] : 0;
    sh[threadIdx.x] = v;
    __syncthreads();
#pragma unroll
    for (int off = 1; off < 1024; off <<= 1) {
        int t = (threadIdx.x >= off) ? sh[threadIdx.x - off] : 0;
        __syncthreads();
        sh[threadIdx.x] += t;
        __syncthreads();
    }
    if (i < N_NODES) g_rowptr[i] = sh[threadIdx.x] - v;   // exclusive
    if (threadIdx.x == 1023) g_bsum[blockIdx.x] = sh[1023];
}

__global__ void scan2_kernel() {   // exclusive scan of NBLK (<=128) block totals
    __shared__ int sh[128];
    int v = (threadIdx.x < NBLK) ? g_bsum[threadIdx.x] : 0;
    sh[threadIdx.x] = v;
    __syncthreads();
#pragma unroll
    for (int off = 1; off < 128; off <<= 1) {
        int t = (threadIdx.x >= off) ? sh[threadIdx.x - off] : 0;
        __syncthreads();
        sh[threadIdx.x] += t;
        __syncthreads();
    }
    if (threadIdx.x < NBLK) g_bsum[threadIdx.x] = sh[threadIdx.x] - v;
}

__global__ void scan3_kernel() {   // add block offsets; init cursors
    int i = blockIdx.x * blockDim.x + threadIdx.x;
    if (i < N_NODES) {
        int rp = g_rowptr[i] + g_bsum[i >> 10];
        g_rowptr[i] = rp;
        g_cnt[i]    = rp;            // reuse as cursor
    }
    if (i == 0) g_rowptr[N_NODES] = N_EDGES;
}

__global__ void permute_kernel(const int* __restrict__ rows, const int* __restrict__ cols,
                               const float* __restrict__ vals) {
    int e = blockIdx.x * blockDim.x + threadIdx.x;
    if (e >= N_EDGES) return;
    int r = rows[e];
    int p = atomicAdd(&g_cnt[r], 1);
    g_ecol[p] = cols[e];
    g_eval[p] = vals[e];
}

// ---------------------------------------------------------------------------
// SpMM gather (no atomics): warp per row; lane owns 2 features (float2).
// Edge (col,val) pairs loaded coalesced in chunks of 32 and broadcast via shfl.
// ---------------------------------------------------------------------------
__global__ void spmm_gather(const float* __restrict__ src, float* __restrict__ dst) {
    int warp = (blockIdx.x * blockDim.x + threadIdx.x) >> 5;
    if (warp >= N_NODES) return;
    int lane = threadIdx.x & 31;

    int s = g_rowptr[warp];
    int e = g_rowptr[warp + 1];

    float2 acc = make_float2(0.f, 0.f);
    for (int base = s; base < e; base += 32) {
        int rem = e - base;
        int n = rem < 32 ? rem : 32;
        int   c = 0;
        float v = 0.f;
        if (lane < n) { c = g_ecol[base + lane]; v = g_eval[base + lane]; }
#pragma unroll 4
        for (int j = 0; j < n; j++) {
            int   cj = __shfl_sync(0xffffffffu, c, j);
            float vj = __shfl_sync(0xffffffffu, v, j);
            float2 m = ((const float2*)(src + (size_t)cj * 64))[lane];
            acc.x = fmaf(vj, m.x, acc.x);
            acc.y = fmaf(vj, m.y, acc.y);
        }
    }
    ((float2*)(dst + (size_t)warp * 64))[lane] = acc;
}

// ---------------------------------------------------------------------------
// Y[M x 64] = act(X[M x K]) @ W[K x 64] + b   via packed FFMA2.
// 256 threads, 128 nodes x 64 cols per block; thread = 4 nodes x 8 cols.
// ---------------------------------------------------------------------------
template <int K, bool RELU_IN>
__global__ void __launch_bounds__(256) gemm64v(const float* __restrict__ X,
                                               const float* __restrict__ W,
                                               const float* __restrict__ b,
                                               float* __restrict__ Y) {
    __shared__ float xs[128][68];   // 68 = pad, keeps rows 16B aligned
    __shared__ float ws[64][64];

    const int tid = threadIdx.x;
    const int m0  = blockIdx.x * 128;
    const int cg  = tid & 7;        // 8 cols:  cg*8 .. cg*8+7  (4 f32x2 pairs)
    const int ng  = tid >> 3;       // 4 nodes: ng*4 .. ng*4+3

    ull acc[4][4];
#pragma unroll
    for (int i = 0; i < 4; i++)
#pragma unroll
        for (int j = 0; j < 4; j++) acc[i][j] = 0ull;

    for (int kc = 0; kc < K; kc += 64) {
        // stage X tile [128 x 64] with float4 loads
#pragma unroll
        for (int t = tid; t < 128 * 16; t += 256) {
            int n = t >> 4, kq = t & 15;
            float4 v = make_float4(0.f, 0.f, 0.f, 0.f);
            if (m0 + n < N_NODES)
                v = *(const float4*)&X[(size_t)(m0 + n) * K + kc + kq * 4];
            if (RELU_IN) {
                v.x = fmaxf(v.x, 0.f); v.y = fmaxf(v.y, 0.f);
                v.z = fmaxf(v.z, 0.f); v.w = fmaxf(v.w, 0.f);
            }
            *(float4*)&xs[n][kq * 4] = v;
        }
        // stage W tile [64 x 64]
#pragma unroll
        for (int t = tid; t < 64 * 16; t += 256) {
            int k = t >> 4, cq = t & 15;
            *(float4*)&ws[k][cq * 4] = *(const float4*)&W[(size_t)(kc + k) * 64 + cq * 4];
        }
        __syncthreads();

#pragma unroll 4
        for (int k = 0; k < 64; k++) {
            const ull* wrow = (const ull*)&ws[k][cg * 8];   // 4 packed pairs
            ull w0 = wrow[0], w1 = wrow[1], w2 = wrow[2], w3 = wrow[3];
#pragma unroll
            for (int i = 0; i < 4; i++) {
                float xv = xs[ng * 4 + i][k];
                ull x2 = pack2(xv, xv);
                ffma2(acc[i][0], x2, w0);
                ffma2(acc[i][1], x2, w1);
                ffma2(acc[i][2], x2, w2);
                ffma2(acc[i][3], x2, w3);
            }
        }
        __syncthreads();
    }

    // epilogue: + bias, store
    float bias[8];
#pragma unroll
    for (int j = 0; j < 8; j++) bias[j] = b[cg * 8 + j];

#pragma unroll
    for (int i = 0; i < 4; i++) {
        int n = m0 + ng * 4 + i;
        if (n < N_NODES) {
            float2 p0 = unpack2(acc[i][0]), p1 = unpack2(acc[i][1]);
            float2 p2 = unpack2(acc[i][2]), p3 = unpack2(acc[i][3]);
            float4 o0 = make_float4(p0.x + bias[0], p0.y + bias[1],
                                    p1.x + bias[2], p1.y + bias[3]);
            float4 o1 = make_float4(p2.x + bias[4], p2.y + bias[5],
                                    p3.x + bias[6], p3.y + bias[7]);
            *(float4*)&Y[(size_t)n * 64 + cg * 8]     = o0;
            *(float4*)&Y[(size_t)n * 64 + cg * 8 + 4] = o1;
        }
    }
}

// ---------------------------------------------------------------------------
// Classifier: logits = H @ Wc + bc, then log_softmax. Warp per node.
// ---------------------------------------------------------------------------
__global__ void classify(const float* __restrict__ H, const float* __restrict__ Wc,
                         const float* __restrict__ bc, float* __restrict__ out) {
    __shared__ float wc[64 * NCLS];
    __shared__ float rowbuf[8][64];

    const int tid = threadIdx.x;
    for (int t = tid; t < 64 * NCLS; t += 256) wc[t] = Wc[t];
    __syncthreads();

    const int w    = tid >> 5;
    const int lane = tid & 31;
    const int node = blockIdx.x * 8 + w;
    if (node >= N_NODES) return;

    if (lane < 16) {
        float4 rv = ((const float4*)(H + (size_t)node * 64))[lane];
        *(float4*)&rowbuf[w][lane * 4] = rv;
    }
    __syncwarp();

    float a0 = bc[lane];                              // cols 0..31
    float a1 = (lane < 8) ? bc[32 + lane] : 0.f;      // cols 32..39
#pragma unroll
    for (int k = 0; k < 64; k++) {
        float r = rowbuf[w][k];
        a0 = fmaf(r, wc[k * NCLS + lane], a0);
        if (lane < 8) a1 = fmaf(r, wc[k * NCLS + 32 + lane], a1);
    }

    float mx = (lane < 8) ? fmaxf(a0, a1) : a0;
#pragma unroll
    for (int o = 16; o > 0; o >>= 1) mx = fmaxf(mx, __shfl_xor_sync(0xffffffffu, mx, o));
    float s = expf(a0 - mx) + ((lane < 8) ? expf(a1 - mx) : 0.f);
#pragma unroll
    for (int o = 16; o > 0; o >>= 1) s += __shfl_xor_sync(0xffffffffu, s, o);
    float lse = mx + logf(s);

    out[(size_t)node * NCLS + lane] = a0 - lse;
    if (lane < 8) out[(size_t)node * NCLS + 32 + lane] = a1 - lse;
}

// ---------------------------------------------------------------------------
extern "C" void kernel_launch(void* const* d_in, const int* in_sizes, int n_in,
                              void* d_out, int out_size) {
    const float* x  = (const float*)d_in[0];
    const int*   er = (const int*)  d_in[1];
    const int*   ec = (const int*)  d_in[2];
    const float* ev = (const float*)d_in[3];
    const float* W1 = (const float*)d_in[4];
    const float* b1 = (const float*)d_in[5];
    const float* W2 = (const float*)d_in[6];
    const float* b2 = (const float*)d_in[7];
    const float* Wc = (const float*)d_in[8];
    const float* bc = (const float*)d_in[9];
    float* out = (float*)d_out;

    float *bufA = nullptr, *bufB = nullptr;
    int* cntp = nullptr;
    cudaGetSymbolAddress((void**)&bufA, g_bufA);
    cudaGetSymbolAddress((void**)&bufB, g_bufB);
    cudaGetSymbolAddress((void**)&cntp, g_cnt);

    const int edgeGrid = (N_EDGES + 255) / 256;
    const int gemmGrid = (N_NODES + 127) / 128;
    const int spmmGrid = (N_NODES * 32 + 255) / 256;   // warp per row

    // ---- CSR build (shared by both SpMMs) ----
    cudaMemsetAsync(cntp, 0, sizeof(int) * N_NODES, 0);
    hist_kernel<<<edgeGrid, 256>>>(er);
    scan1_kernel<<<NBLK, 1024>>>();
    scan2_kernel<<<1, 128>>>();
    scan3_kernel<<<(N_NODES + 255) / 256, 256>>>();
    permute_kernel<<<edgeGrid, 256>>>(er, ec, ev);

    // ---- GCN pipeline ----
    gemm64v<IN_DIM, false><<<gemmGrid, 256>>>(x, W1, b1, bufA);      // support1
    spmm_gather<<<spmmGrid, 256>>>(bufA, bufB);                      // agg1
    gemm64v<HID, true><<<gemmGrid, 256>>>(bufB, W2, b2, bufA);       // support2 (relu fused)
    spmm_gather<<<spmmGrid, 256>>>(bufA, bufB);                      // agg2
    classify<<<(N_NODES + 7) / 8, 256>>>(bufB, Wc, bc, out);         // logits + log_softmax
}

// round 4
// speedup vs baseline: 1.2605x; 1.0716x over previous
#include <cuda_runtime.h>
#include <math.h>

#define N_NODES 100000
#define N_EDGES 1600000
#define IN_DIM 128
#define HID 64
#define NCLS 40
#define NBLK ((N_NODES + 1023) / 1024)           // 98 scan blocks
#define PERM_GRID ((N_EDGES + 255) / 256)         // 6250
#define GEMM_GRID ((N_NODES + 127) / 128)         // 782

typedef unsigned long long ull;

// Scratch (static device arrays: allowed; no runtime allocation)
__device__ float g_bufA[(size_t)N_NODES * HID];
__device__ float g_bufB[(size_t)N_NODES * HID];
__device__ int   g_cnt[N_NODES];                  // histogram, then cursors
__device__ int   g_rowptr[N_NODES + 1];
__device__ int   g_bsum[NBLK];
__device__ ull   g_ecv[N_EDGES];                  // CSR-permuted (col, val) packed

// ---------------------------------------------------------------------------
// f32x2 packed helpers (Blackwell FFMA2 — only reachable via PTX)
// ---------------------------------------------------------------------------
__device__ __forceinline__ ull pack2(float x, float y) {
    ull r; asm("mov.b64 %0, {%1, %2};" : "=l"(r) : "f"(x), "f"(y)); return r;
}
__device__ __forceinline__ void ffma2(ull& d, ull a, ull b) {
    asm("fma.rn.f32x2 %0, %1, %2, %0;" : "+l"(d) : "l"(a), "l"(b));
}
__device__ __forceinline__ float2 unpack2(ull a) {
    float2 f; asm("mov.b64 {%0, %1}, %2;" : "=f"(f.x), "=f"(f.y) : "l"(a)); return f;
}

// ---------------------------------------------------------------------------
// CSR build: histogram -> 3-pass exclusive scan
// ---------------------------------------------------------------------------
__global__ void hist_kernel(const int* __restrict__ rows) {
    int e = blockIdx.x * blockDim.x + threadIdx.x;
    if (e < N_EDGES) atomicAdd(&g_cnt[rows[e]], 1);
}

__global__ void scan1_kernel() {   // per-1024-block exclusive scan + block totals
    __shared__ int sh[1024];
    int i = blockIdx.x * 1024 + threadIdx.x;
    int v = (i < N_NODES) ? g_cnt[i] : 0;
    sh[threadIdx.x] = v;
    __syncthreads();
#pragma unroll
    for (int off = 1; off < 1024; off <<= 1) {
        int t = (threadIdx.x >= off) ? sh[threadIdx.x - off] : 0;
        __syncthreads();
        sh[threadIdx.x] += t;
        __syncthreads();
    }
    if (i < N_NODES) g_rowptr[i] = sh[threadIdx.x] - v;   // exclusive
    if (threadIdx.x == 1023) g_bsum[blockIdx.x] = sh[1023];
}

__global__ void scan2_kernel() {   // exclusive scan of NBLK (<=128) block totals
    __shared__ int sh[128];
    int v = (threadIdx.x < NBLK) ? g_bsum[threadIdx.x] : 0;
    sh[threadIdx.x] = v;
    __syncthreads();
#pragma unroll
    for (int off = 1; off < 128; off <<= 1) {
        int t = (threadIdx.x >= off) ? sh[threadIdx.x - off] : 0;
        __syncthreads();
        sh[threadIdx.x] += t;
        __syncthreads();
    }
    if (threadIdx.x < NBLK) g_bsum[threadIdx.x] = sh[threadIdx.x] - v;
}

__global__ void scan3_kernel() {   // add block offsets; init cursors
    int i = blockIdx.x * blockDim.x + threadIdx.x;
    if (i < N_NODES) {
        int rp = g_rowptr[i] + g_bsum[i >> 10];
        g_rowptr[i] = rp;
        g_cnt[i]    = rp;            // reuse as cursor
    }
    if (i == 0) g_rowptr[N_NODES] = N_EDGES;
}

// ---------------------------------------------------------------------------
// FUSED: permute (edge scatter into CSR order) || gemm1 (x @ W1 + b1).
// The two are independent; block-range split runs them concurrently,
// hiding the permute scatter behind the dense GEMM.
// ---------------------------------------------------------------------------
__global__ void __launch_bounds__(256) permute_gemm1(
        const int* __restrict__ rows, const int* __restrict__ cols,
        const float* __restrict__ vals,
        const float* __restrict__ X, const float* __restrict__ W,
        const float* __restrict__ b, float* __restrict__ Y) {
    __shared__ float xs[128][68];
    __shared__ float ws[64][64];

    const int tid = threadIdx.x;

    if (blockIdx.x < PERM_GRID) {
        // ---- permute branch ----
        int e = blockIdx.x * 256 + tid;
        if (e < N_EDGES) {
            int r = rows[e];
            int p = atomicAdd(&g_cnt[r], 1);
            g_ecv[p] = ((ull)__float_as_uint(vals[e]) << 32) | (unsigned)cols[e];
        }
        return;
    }

    // ---- gemm1 branch: Y[128 x 64] tile = X[128 x 128] @ W[128 x 64] + b ----
    const int m0 = (blockIdx.x - PERM_GRID) * 128;
    const int cg = tid & 7;        // 8 cols:  cg*8 .. cg*8+7  (4 f32x2 pairs)
    const int ng = tid >> 3;       // 4 nodes: ng*4 .. ng*4+3

    ull acc[4][4];
#pragma unroll
    for (int i = 0; i < 4; i++)
#pragma unroll
        for (int j = 0; j < 4; j++) acc[i][j] = 0ull;

    for (int kc = 0; kc < IN_DIM; kc += 64) {
#pragma unroll
        for (int t = tid; t < 128 * 16; t += 256) {
            int n = t >> 4, kq = t & 15;
            float4 v = make_float4(0.f, 0.f, 0.f, 0.f);
            if (m0 + n < N_NODES)
                v = *(const float4*)&X[(size_t)(m0 + n) * IN_DIM + kc + kq * 4];
            *(float4*)&xs[n][kq * 4] = v;
        }
#pragma unroll
        for (int t = tid; t < 64 * 16; t += 256) {
            int k = t >> 4, cq = t & 15;
            *(float4*)&ws[k][cq * 4] = *(const float4*)&W[(size_t)(kc + k) * 64 + cq * 4];
        }
        __syncthreads();

#pragma unroll 4
        for (int k = 0; k < 64; k++) {
            const ull* wrow = (const ull*)&ws[k][cg * 8];
            ull w0 = wrow[0], w1 = wrow[1], w2 = wrow[2], w3 = wrow[3];
#pragma unroll
            for (int i = 0; i < 4; i++) {
                float xv = xs[ng * 4 + i][k];
                ull x2 = pack2(xv, xv);
                ffma2(acc[i][0], x2, w0);
                ffma2(acc[i][1], x2, w1);
                ffma2(acc[i][2], x2, w2);
                ffma2(acc[i][3], x2, w3);
            }
        }
        __syncthreads();
    }

    float bias[8];
#pragma unroll
    for (int j = 0; j < 8; j++) bias[j] = b[cg * 8 + j];

#pragma unroll
    for (int i = 0; i < 4; i++) {
        int n = m0 + ng * 4 + i;
        if (n < N_NODES) {
            float2 p0 = unpack2(acc[i][0]), p1 = unpack2(acc[i][1]);
            float2 p2 = unpack2(acc[i][2]), p3 = unpack2(acc[i][3]);
            float4 o0 = make_float4(p0.x + bias[0], p0.y + bias[1],
                                    p1.x + bias[2], p1.y + bias[3]);
            float4 o1 = make_float4(p2.x + bias[4], p2.y + bias[5],
                                    p3.x + bias[6], p3.y + bias[7]);
            *(float4*)&Y[(size_t)n * 64 + cg * 8]     = o0;
            *(float4*)&Y[(size_t)n * 64 + cg * 8 + 4] = o1;
        }
    }
}

// ---------------------------------------------------------------------------
// Per-row CSR gather: warp computes a 64-wide aggregated row (float2 per lane).
// Packed (col,val) loaded coalesced as LDG.64; dual accumulators break the
// FFMA dependency chain.
// ---------------------------------------------------------------------------
__device__ __forceinline__ float2 row_gather(const float* __restrict__ src,
                                             int s, int e, int lane) {
    float2 a0 = make_float2(0.f, 0.f);
    float2 a1 = make_float2(0.f, 0.f);
    int base = s;
    // full 32-edge chunks
    for (; base + 32 <= e; base += 32) {
        ull p = __ldg(&g_ecv[base + lane]);
#pragma unroll
        for (int j = 0; j < 32; j += 2) {
            ull b0 = __shfl_sync(0xffffffffu, p, j);
            ull b1 = __shfl_sync(0xffffffffu, p, j + 1);
            int   c0 = (int)(unsigned)b0;
            float v0 = __uint_as_float((unsigned)(b0 >> 32));
            int   c1 = (int)(unsigned)b1;
            float v1 = __uint_as_float((unsigned)(b1 >> 32));
            float2 m0 = ((const float2*)(src + (size_t)c0 * 64))[lane];
            float2 m1 = ((const float2*)(src + (size_t)c1 * 64))[lane];
            a0.x = fmaf(v0, m0.x, a0.x); a0.y = fmaf(v0, m0.y, a0.y);
            a1.x = fmaf(v1, m1.x, a1.x); a1.y = fmaf(v1, m1.y, a1.y);
        }
    }
    // tail (common case: avg degree 16)
    int n = e - base;
    if (n > 0) {
        ull p = (lane < n) ? __ldg(&g_ecv[base + lane]) : 0ull;
        int j = 0;
        for (; j + 1 < n; j += 2) {
            ull b0 = __shfl_sync(0xffffffffu, p, j);
            ull b1 = __shfl_sync(0xffffffffu, p, j + 1);
            int   c0 = (int)(unsigned)b0;
            float v0 = __uint_as_float((unsigned)(b0 >> 32));
            int   c1 = (int)(unsigned)b1;
            float v1 = __uint_as_float((unsigned)(b1 >> 32));
            float2 m0 = ((const float2*)(src + (size_t)c0 * 64))[lane];
            float2 m1 = ((const float2*)(src + (size_t)c1 * 64))[lane];
            a0.x = fmaf(v0, m0.x, a0.x); a0.y = fmaf(v0, m0.y, a0.y);
            a1.x = fmaf(v1, m1.x, a1.x); a1.y = fmaf(v1, m1.y, a1.y);
        }
        if (j < n) {
            ull b0 = __shfl_sync(0xffffffffu, p, j);
            int   c0 = (int)(unsigned)b0;
            float v0 = __uint_as_float((unsigned)(b0 >> 32));
            float2 m0 = ((const float2*)(src + (size_t)c0 * 64))[lane];
            a0.x = fmaf(v0, m0.x, a0.x); a0.y = fmaf(v0, m0.y, a0.y);
        }
    }
    a0.x += a1.x; a0.y += a1.y;
    return a0;
}

__global__ void spmm_gather(const float* __restrict__ src, float* __restrict__ dst) {
    int warp = (blockIdx.x * blockDim.x + threadIdx.x) >> 5;
    if (warp >= N_NODES) return;
    int lane = threadIdx.x & 31;
    int s = __ldg(&g_rowptr[warp]);
    int e = __ldg(&g_rowptr[warp + 1]);
    float2 acc = row_gather(src, s, e, lane);
    ((float2*)(dst + (size_t)warp * 64))[lane] = acc;
}

// ---------------------------------------------------------------------------
// FUSED: spmm2 + classifier + log-softmax. Warp per node: gather agg2 row,
// stage it in smem, 64x40 GEMV against smem Wc, warp log-softmax, write out.
// Avoids the 25.6 MB agg2 write + read roundtrip entirely.
// ---------------------------------------------------------------------------
__global__ void __launch_bounds__(512) spmm_classify(const float* __restrict__ src,
                                                     const float* __restrict__ Wc,
                                                     const float* __restrict__ bc,
                                                     float* __restrict__ out) {
    __shared__ float wc[64 * NCLS];
    __shared__ float rowbuf[16][64];

    const int tid = threadIdx.x;
    for (int t = tid; t < 64 * NCLS; t += 512) wc[t] = Wc[t];
    __syncthreads();

    const int w    = tid >> 5;
    const int lane = tid & 31;
    const int node = blockIdx.x * 16 + w;
    if (node >= N_NODES) return;

    int s = __ldg(&g_rowptr[node]);
    int e = __ldg(&g_rowptr[node + 1]);
    float2 acc = row_gather(src, s, e, lane);
    *(float2*)&rowbuf[w][lane * 2] = acc;
    __syncwarp();

    float a0 = bc[lane];                              // cols 0..31
    float a1 = (lane < 8) ? bc[32 + lane] : 0.f;      // cols 32..39
#pragma unroll
    for (int k = 0; k < 64; k++) {
        float r = rowbuf[w][k];
        a0 = fmaf(r, wc[k * NCLS + lane], a0);
        if (lane < 8) a1 = fmaf(r, wc[k * NCLS + 32 + lane], a1);
    }

    float mx = (lane < 8) ? fmaxf(a0, a1) : a0;
#pragma unroll
    for (int o = 16; o > 0; o >>= 1) mx = fmaxf(mx, __shfl_xor_sync(0xffffffffu, mx, o));
    float sum = expf(a0 - mx) + ((lane < 8) ? expf(a1 - mx) : 0.f);
#pragma unroll
    for (int o = 16; o > 0; o >>= 1) sum += __shfl_xor_sync(0xffffffffu, sum, o);
    float lse = mx + logf(sum);

    out[(size_t)node * NCLS + lane] = a0 - lse;
    if (lane < 8) out[(size_t)node * NCLS + 32 + lane] = a1 - lse;
}

// ---------------------------------------------------------------------------
// Y[M x 64] = relu(X[M x 64]) @ W[64 x 64] + b   (layer-2 dense, FFMA2)
// ---------------------------------------------------------------------------
__global__ void __launch_bounds__(256) gemm64v2(const float* __restrict__ X,
                                                const float* __restrict__ W,
                                                const float* __restrict__ b,
                                                float* __restrict__ Y) {
    __shared__ float xs[128][68];
    __shared__ float ws[64][64];

    const int tid = threadIdx.x;
    const int m0  = blockIdx.x * 128;
    const int cg  = tid & 7;
    const int ng  = tid >> 3;

    ull acc[4][4];
#pragma unroll
    for (int i = 0; i < 4; i++)
#pragma unroll
        for (int j = 0; j < 4; j++) acc[i][j] = 0ull;

#pragma unroll
    for (int t = tid; t < 128 * 16; t += 256) {
        int n = t >> 4, kq = t & 15;
        float4 v = make_float4(0.f, 0.f, 0.f, 0.f);
        if (m0 + n < N_NODES)
            v = *(const float4*)&X[(size_t)(m0 + n) * 64 + kq * 4];
        v.x = fmaxf(v.x, 0.f); v.y = fmaxf(v.y, 0.f);
        v.z = fmaxf(v.z, 0.f); v.w = fmaxf(v.w, 0.f);
        *(float4*)&xs[n][kq * 4] = v;
    }
#pragma unroll
    for (int t = tid; t < 64 * 16; t += 256) {
        int k = t >> 4, cq = t & 15;
        *(float4*)&ws[k][cq * 4] = *(const float4*)&W[(size_t)k * 64 + cq * 4];
    }
    __syncthreads();

#pragma unroll 4
    for (int k = 0; k < 64; k++) {
        const ull* wrow = (const ull*)&ws[k][cg * 8];
        ull w0 = wrow[0], w1 = wrow[1], w2 = wrow[2], w3 = wrow[3];
#pragma unroll
        for (int i = 0; i < 4; i++) {
            float xv = xs[ng * 4 + i][k];
            ull x2 = pack2(xv, xv);
            ffma2(acc[i][0], x2, w0);
            ffma2(acc[i][1], x2, w1);
            ffma2(acc[i][2], x2, w2);
            ffma2(acc[i][3], x2, w3);
        }
    }

    float bias[8];
#pragma unroll
    for (int j = 0; j < 8; j++) bias[j] = b[cg * 8 + j];

#pragma unroll
    for (int i = 0; i < 4; i++) {
        int n = m0 + ng * 4 + i;
        if (n < N_NODES) {
            float2 p0 = unpack2(acc[i][0]), p1 = unpack2(acc[i][1]);
            float2 p2 = unpack2(acc[i][2]), p3 = unpack2(acc[i][3]);
            float4 o0 = make_float4(p0.x + bias[0], p0.y + bias[1],
                                    p1.x + bias[2], p1.y + bias[3]);
            float4 o1 = make_float4(p2.x + bias[4], p2.y + bias[5],
                                    p3.x + bias[6], p3.y + bias[7]);
            *(float4*)&Y[(size_t)n * 64 + cg * 8]     = o0;
            *(float4*)&Y[(size_t)n * 64 + cg * 8 + 4] = o1;
        }
    }
}

// ---------------------------------------------------------------------------
extern "C" void kernel_launch(void* const* d_in, const int* in_sizes, int n_in,
                              void* d_out, int out_size) {
    const float* x  = (const float*)d_in[0];
    const int*   er = (const int*)  d_in[1];
    const int*   ec = (const int*)  d_in[2];
    const float* ev = (const float*)d_in[3];
    const float* W1 = (const float*)d_in[4];
    const float* b1 = (const float*)d_in[5];
    const float* W2 = (const float*)d_in[6];
    const float* b2 = (const float*)d_in[7];
    const float* Wc = (const float*)d_in[8];
    const float* bc = (const float*)d_in[9];
    float* out = (float*)d_out;

    float *bufA = nullptr, *bufB = nullptr;
    int* cntp = nullptr;
    cudaGetSymbolAddress((void**)&bufA, g_bufA);
    cudaGetSymbolAddress((void**)&bufB, g_bufB);
    cudaGetSymbolAddress((void**)&cntp, g_cnt);

    const int edgeGrid = (N_EDGES + 255) / 256;
    const int spmmGrid = (N_NODES * 32 + 255) / 256;     // warp per row

    // ---- CSR build prologue ----
    cudaMemsetAsync(cntp, 0, sizeof(int) * N_NODES, 0);
    hist_kernel<<<edgeGrid, 256>>>(er);
    scan1_kernel<<<NBLK, 1024>>>();
    scan2_kernel<<<1, 128>>>();
    scan3_kernel<<<(N_NODES + 255) / 256, 256>>>();

    // ---- permute (edges -> CSR) fused with gemm1 (support1 = x@W1+b1) ----
    permute_gemm1<<<PERM_GRID + GEMM_GRID, 256>>>(er, ec, ev, x, W1, b1, bufA);

    // ---- agg1 = A_sp @ support1 ----
    spmm_gather<<<spmmGrid, 256>>>(bufA, bufB);

    // ---- support2 = relu(agg1) @ W2 + b2 ----
    gemm64v2<<<GEMM_GRID, 256>>>(bufB, W2, b2, bufA);

    // ---- agg2 + classifier + log-softmax (fused) ----
    spmm_classify<<<(N_NODES + 15) / 16, 512>>>(bufA, Wc, bc, out);
}